// round 11
// baseline (speedup 1.0000x reference)
#include <cuda_runtime.h>

#define NN 512
#define TP 16

typedef unsigned long long ull;

// ---------- f32x2 packed helpers ----------
__device__ __forceinline__ ull pk2(float lo, float hi) {
    ull r; asm("mov.b64 %0, {%1, %2};" : "=l"(r) : "f"(lo), "f"(hi)); return r;
}
__device__ __forceinline__ void upk2(float& lo, float& hi, ull v) {
    asm("mov.b64 {%0, %1}, %2;" : "=f"(lo), "=f"(hi) : "l"(v));
}
__device__ __forceinline__ void ffma2(ull& acc, ull a, ull b) {
    asm("fma.rn.f32x2 %0, %1, %2, %0;" : "+l"(acc) : "l"(a), "l"(b));
}

// ---------------- scratch ----------------
__device__ float g_XW1a[NN * TP * 32];
__device__ float g_XW1b[NN * TP * 32];
__device__ float g_XW2a[NN * TP * 32];
__device__ float g_XW2b[NN * TP * 32];
__device__ float g_Q[NN * 32];
__device__ float g_QB[NN * TP];
__device__ float g_RA[NN * TP];
__device__ float g_U1[NN * 256];    // U1[a][t*16+i] = sum_h Q[a,h] W1[i,t,h]
__device__ float g_U2[NN * 256];    // same with W1[i+16]
__device__ float g_L1[NN * NN];     // logits1 -> s1
__device__ float g_L2T[NN * NN];    // logits2^T -> s2^T
__device__ float g_r1[NN * TP];
__device__ float g_c2[NN * TP];
__device__ float g_G1p[8 * NN * 240];   // G1 partials per m-chunk
__device__ float g_G2p[8 * NN * 240];

// ---------------- k1: XW1a/b, XW2a/b, Q, QB, RA, U1/U2 ----------------
__global__ void k1_precompute(const float* __restrict__ x,
                              const float* __restrict__ W1,
                              const float* __restrict__ W2,
                              const float* __restrict__ W3) {
    int n0 = blockIdx.x * 4;
    __shared__ float xs[4][16];
    __shared__ float Qsm[4][32];
    int tid = threadIdx.x;
    if (tid < 64) xs[tid / 16][tid % 16] = x[(n0 + tid / 16) * 16 + (tid % 16)];
    __syncthreads();

    for (int th = tid; th < 512; th += 256) {
        float a1[4] = {0,0,0,0}, b1[4] = {0,0,0,0};
        float a2[4] = {0,0,0,0}, b2[4] = {0,0,0,0};
        for (int i = 0; i < 16; i++) {
            float w1a = W1[i * 512 + th];
            float w1b = W1[(i + 16) * 512 + th];
            float w2a = W2[i * 512 + th];
            float w2b = W2[(i + 16) * 512 + th];
#pragma unroll
            for (int j = 0; j < 4; j++) {
                float xv = xs[j][i];
                a1[j] += xv * w1a; b1[j] += xv * w1b;
                a2[j] += xv * w2a; b2[j] += xv * w2b;
            }
        }
#pragma unroll
        for (int j = 0; j < 4; j++) {
            g_XW1a[(n0 + j) * 512 + th] = a1[j];
            g_XW1b[(n0 + j) * 512 + th] = b1[j];
            g_XW2a[(n0 + j) * 512 + th] = a2[j];
            g_XW2b[(n0 + j) * 512 + th] = b2[j];
        }
    }
    if (tid < 32) {
#pragma unroll
        for (int j = 0; j < 4; j++) {
            float acc = 0.f;
            for (int i = 0; i < 16; i++) acc += xs[j][i] * W3[i * 32 + tid];
            g_Q[(n0 + j) * 32 + tid] = acc;
            Qsm[j][tid] = acc;
        }
    }
    __syncthreads();
    if (tid < 64) {
        int n = n0 + tid / 16, t = tid % 16;
        const float* q  = g_Q + n * 32;
        const float* wa = g_XW1a + n * 512 + t * 32;
        const float* wb = g_XW1b + n * 512 + t * 32;
        float ra = 0.f, qb = 0.f;
#pragma unroll
        for (int h = 0; h < 32; h++) { float qv = q[h]; ra += qv * wa[h]; qb += qv * wb[h]; }
        g_RA[n * 16 + t] = ra;
        g_QB[n * 16 + t] = qb;
    }
    // U1/U2: U[a][t*16+i] = sum_h Q[a,h] * W1[i(,+16),t,h]
    {
        int t = tid >> 4, i = tid & 15;
        const float* w1a = W1 + i * 512 + t * 32;
        const float* w1b = W1 + (i + 16) * 512 + t * 32;
        float u1[4] = {0,0,0,0}, u2[4] = {0,0,0,0};
#pragma unroll 8
        for (int h = 0; h < 32; h++) {
            float wa_ = w1a[h], wb_ = w1b[h];
#pragma unroll
            for (int j = 0; j < 4; j++) {
                float qv = Qsm[j][h];
                u1[j] += qv * wa_;
                u2[j] += qv * wb_;
            }
        }
#pragma unroll
        for (int j = 0; j < 4; j++) {
            g_U1[(n0 + j) * 256 + t * 16 + i] = u1[j];
            g_U2[(n0 + j) * 256 + t * 16 + i] = u2[j];
        }
    }
}

// ---------------- k2: factored logits, thread-per-(a,b), no shuffles ----------------
// grid (32 b-tiles of 16, 32 a-tiles of 16), 256 threads.
struct K2S {
    ull U1p[16][17][8];     // [a][t][ipair], row pad 17 for bank split
    ull U2p[16][17][8];
    float adjR[16][241];    // adj[a, b0..b0+15, t] contiguous per a
    float adjC[16][241];    // adj[b, a0..a0+15, t] contiguous per b
    ull xp[16][8];
    float QBs[16][16];
    float RAs[16][16];
};

__global__ void __launch_bounds__(256) k2_logits(const float* __restrict__ adj,
                                                 const float* __restrict__ x) {
    extern __shared__ char sraw[];
    K2S& S = *reinterpret_cast<K2S*>(sraw);
    int tid = threadIdx.x;
    int a0 = blockIdx.y * 16, b0 = blockIdx.x * 16;
    int bid = blockIdx.y * 32 + blockIdx.x;
    if (bid < 32)      g_r1[bid * 256 + tid] = 0.f;
    else if (bid < 64) g_c2[(bid - 32) * 256 + tid] = 0.f;

    // stage packed U rows
    for (int idx = tid; idx < 2048; idx += 256) {
        int a = idx >> 7, p = idx & 127;
        int t = p >> 3, ip = p & 7;
        float2 v1 = *(const float2*)(g_U1 + (a0 + a) * 256 + t * 16 + ip * 2);
        float2 v2 = *(const float2*)(g_U2 + (a0 + a) * 256 + t * 16 + ip * 2);
        S.U1p[a][t][ip] = pk2(v1.x, v1.y);
        S.U2p[a][t][ip] = pk2(v2.x, v2.y);
    }
    // stage adj tiles (both contiguous 240-float runs, 16B aligned)
    for (int idx = tid; idx < 960; idx += 256) {
        int r = idx / 60, q = (idx % 60) * 4;
        float4 vR = *(const float4*)(adj + ((long)(a0 + r) * 512 + b0) * 15 + q);
        float4 vC = *(const float4*)(adj + ((long)(b0 + r) * 512 + a0) * 15 + q);
        S.adjR[r][q] = vR.x; S.adjR[r][q+1] = vR.y; S.adjR[r][q+2] = vR.z; S.adjR[r][q+3] = vR.w;
        S.adjC[r][q] = vC.x; S.adjC[r][q+1] = vC.y; S.adjC[r][q+2] = vC.z; S.adjC[r][q+3] = vC.w;
    }
    if (tid < 128) {
        int b = tid >> 3, ip = tid & 7;
        float2 v = *(const float2*)(x + (b0 + b) * 16 + ip * 2);
        S.xp[b][ip] = pk2(v.x, v.y);
    }
    {
        int a = tid >> 4, t = tid & 15;
        S.QBs[a][t] = g_QB[(a0 + a) * 16 + t];
        S.RAs[a][t] = g_RA[(a0 + a) * 16 + t];
    }
    __syncthreads();

    int a = tid >> 4, bsub = tid & 15;
    int ag = a0 + a, bg = b0 + bsub;
    float diagF = (ag == bg) ? 1.f : 0.f;

    ull xr[8];
    {
        ulonglong2* d = (ulonglong2*)xr;
        const ulonglong2* s = (const ulonglong2*)S.xp[bsub];
        d[0] = s[0]; d[1] = s[1]; d[2] = s[2]; d[3] = s[3];
    }

    // pass A: w1 = sum_t ar_t * U1[a,t,:],  accQB = sum_t ac_t * QB[a,t]
    ull w1p[8];
#pragma unroll
    for (int ip = 0; ip < 8; ip++) w1p[ip] = 0ull;
    float accQB = 0.f;
#pragma unroll
    for (int t = 0; t < 16; t++) {
        float ar = (t < 15) ? S.adjR[a][bsub * 15 + t] : diagF;
        float ac = (t < 15) ? S.adjC[bsub][a * 15 + t] : diagF;
        ull arp = pk2(ar, ar);
        const ulonglong2* u = (const ulonglong2*)S.U1p[a][t];
        ulonglong2 u0 = u[0], u1 = u[1], u2 = u[2], u3 = u[3];
        ffma2(w1p[0], arp, u0.x); ffma2(w1p[1], arp, u0.y);
        ffma2(w1p[2], arp, u1.x); ffma2(w1p[3], arp, u1.y);
        ffma2(w1p[4], arp, u2.x); ffma2(w1p[5], arp, u2.y);
        ffma2(w1p[6], arp, u3.x); ffma2(w1p[7], arp, u3.y);
        accQB += ac * S.QBs[a][t];
    }
    {
        ull dot = 0ull;
#pragma unroll
        for (int ip = 0; ip < 8; ip++) ffma2(dot, xr[ip], w1p[ip]);
        float lo, hi; upk2(lo, hi, dot);
        g_L1[ag * 512 + bg] = lo + hi + accQB;
    }

    // pass B: w2 with U2, accRA with RA
    ull w2p[8];
#pragma unroll
    for (int ip = 0; ip < 8; ip++) w2p[ip] = 0ull;
    float accRA = 0.f;
#pragma unroll
    for (int t = 0; t < 16; t++) {
        float ar = (t < 15) ? S.adjR[a][bsub * 15 + t] : diagF;
        float ac = (t < 15) ? S.adjC[bsub][a * 15 + t] : diagF;
        ull arp = pk2(ar, ar);
        const ulonglong2* u = (const ulonglong2*)S.U2p[a][t];
        ulonglong2 u0 = u[0], u1 = u[1], u2 = u[2], u3 = u[3];
        ffma2(w2p[0], arp, u0.x); ffma2(w2p[1], arp, u0.y);
        ffma2(w2p[2], arp, u1.x); ffma2(w2p[3], arp, u1.y);
        ffma2(w2p[4], arp, u2.x); ffma2(w2p[5], arp, u2.y);
        ffma2(w2p[6], arp, u3.x); ffma2(w2p[7], arp, u3.y);
        accRA += ac * S.RAs[a][t];
    }
    {
        ull dot = 0ull;
#pragma unroll
        for (int ip = 0; ip < 8; ip++) ffma2(dot, xr[ip], w2p[ip]);
        float lo, hi; upk2(lo, hi, dot);
        g_L2T[ag * 512 + bg] = lo + hi + accRA;
    }
}

// ---------------- k5: row softmax ----------------
__global__ void k5_softmax() {
    int r = blockIdx.x;
    float* row = (r < 512) ? (g_L1 + r * 512) : (g_L2T + (r - 512) * 512);
    int tid = threadIdx.x;
    __shared__ float red[8];
    float v0 = row[tid], v1 = row[tid + 256];
    float m = fmaxf(v0, v1);
#pragma unroll
    for (int o = 16; o; o >>= 1) m = fmaxf(m, __shfl_xor_sync(0xffffffffu, m, o));
    if ((tid & 31) == 0) red[tid >> 5] = m;
    __syncthreads();
    float bm = red[0];
#pragma unroll
    for (int i = 1; i < 8; i++) bm = fmaxf(bm, red[i]);
    float e0 = __expf(v0 - bm), e1 = __expf(v1 - bm);
    float s = e0 + e1;
#pragma unroll
    for (int o = 16; o; o >>= 1) s += __shfl_xor_sync(0xffffffffu, s, o);
    __syncthreads();
    if ((tid & 31) == 0) red[tid >> 5] = s;
    __syncthreads();
    float bs = red[0] + red[1] + red[2] + red[3] + red[4] + red[5] + red[6] + red[7];
    float inv = 1.0f / bs;
    row[tid] = e0 * inv;
    row[tid + 256] = e1 * inv;
}

// ---------------- k6G: merged r1/c2 + G contraction (one launch) ----------------
// blocks 0..511: k6r role (m-tile 16, n-tile 32). blocks 512..639: kG role (m-chunk 64, n-tile 32).
struct SmR { float s1[32][17]; float s2[32][17]; };
struct SmG { float s1[32][64]; float s2[32][64]; ull xp[64][8]; };

__global__ void __launch_bounds__(480) k6G(const float* __restrict__ adj,
                                           const float* __restrict__ x) {
    __shared__ union { SmR r; SmG g; } U;
    int bid = blockIdx.x;
    int tid = threadIdx.x;

    if (bid < 512) {
        // ---- k6r role: r1/c2 via transpose-tiled coalesced adj reads ----
        int m0 = (bid >> 4) * 16, n0 = (bid & 15) * 32;
        for (int idx = tid; idx < 512; idx += 480) {
            int n = idx >> 4, ml = idx & 15;
            U.r.s1[n][ml] = g_L1[(n0 + n) * 512 + m0 + ml];
            U.r.s2[n][ml] = g_L2T[(n0 + n) * 512 + m0 + ml];
        }
        __syncthreads();
        int dn = m0 - n0;
        if ((dn == 0 || dn == 16) && tid < 16) {
            int n = dn + tid;
            atomicAdd(&g_r1[(n0 + n) * 16 + 15], U.r.s1[n][tid]);
            atomicAdd(&g_c2[(n0 + n) * 16 + 15], U.r.s2[n][tid]);
        }
        int n = tid / 15, t = tid - n * 15;
        const float* base = adj + ((long)m0 * 512 + n0) * 15 + tid;
        float r1p = 0.f, c2p = 0.f;
#pragma unroll
        for (int ml = 0; ml < 16; ml++) {
            float v = __ldg(base + ml * 7680);
            r1p += U.r.s1[n][ml] * v;
            c2p += U.r.s2[n][ml] * v;
        }
        atomicAdd(&g_r1[(n0 + n) * 16 + t], r1p);
        atomicAdd(&g_c2[(n0 + n) * 16 + t], c2p);
    } else {
        // ---- kG role: G[n,t,i] = sum_m (s*adj)[n,m,t] x[m,i] ----
        int id = bid - 512;
        int m0 = (id >> 4) * 64, n0 = (id & 15) * 32;
        int chunk = id >> 4;
        for (int idx = tid; idx < 2048; idx += 480) {
            int n = idx >> 6, ml = idx & 63;
            U.g.s1[n][ml] = g_L1[(n0 + n) * 512 + m0 + ml];
            U.g.s2[n][ml] = g_L2T[(n0 + n) * 512 + m0 + ml];
        }
        for (int idx = tid; idx < 512; idx += 480) {
            int ml = idx >> 3, ip = idx & 7;
            float2 v = *(const float2*)(x + (m0 + ml) * 16 + ip * 2);
            U.g.xp[ml][ip] = pk2(v.x, v.y);
        }
        __syncthreads();

        int n = tid / 15, t = tid - n * 15;
        ull G1[8], G2[8];
#pragma unroll
        for (int ip = 0; ip < 8; ip++) { G1[ip] = 0ull; G2[ip] = 0ull; }

        const float* ap = adj + (long)(n0 + n) * 7680 + (long)m0 * 15 + t;
#pragma unroll 8
        for (int ml = 0; ml < 64; ml++) {
            float av = __ldg(ap + ml * 15);
            float p1 = U.g.s1[n][ml] * av;
            float p2 = U.g.s2[n][ml] * av;
            ull p1p = pk2(p1, p1), p2p = pk2(p2, p2);
#pragma unroll
            for (int ip = 0; ip < 8; ip++) {
                ull xv = U.g.xp[ml][ip];
                ffma2(G1[ip], p1p, xv);
                ffma2(G2[ip], p2p, xv);
            }
        }
        long base = ((long)chunk * 512 + n0 + n) * 240 + t * 16;
        float* d1 = g_G1p + base;
        float* d2 = g_G2p + base;
#pragma unroll
        for (int q = 0; q < 4; q++) {
            ulonglong2 v1; v1.x = G1[2 * q]; v1.y = G1[2 * q + 1];
            ulonglong2 v2; v2.x = G2[2 * q]; v2.y = G2[2 * q + 1];
            *(ulonglong2*)(d1 + q * 4) = v1;
            *(ulonglong2*)(d2 + q * 4) = v2;
        }
    }
}

// ---------------- kEpi: reduce G partials + tiny GEMM + r1/c2 tail + lrelu ----------------
struct EpiS {
    float Gs1[16][240];
    float Gs2[16][240];
    float W2sa[240][32];
    float W2sb[240][32];
    float r1s[16][16], c2s[16][16];
};

__global__ void __launch_bounds__(512) kEpi(float* __restrict__ out,
                                            const float* __restrict__ W2) {
    extern __shared__ char smem_raw[];
    EpiS& S = *reinterpret_cast<EpiS*>(smem_raw);
    int n0 = blockIdx.x * 16;
    int tid = threadIdx.x;

    for (int idx = tid; idx < 7680; idx += 512) {
        int ti = idx >> 5, d = idx & 31;
        int i = ti & 15, t = ti >> 4;
        S.W2sa[ti][d] = W2[i * 512 + t * 32 + d];
        S.W2sb[ti][d] = W2[(i + 16) * 512 + t * 32 + d];
    }
    for (int idx = tid; idx < 3840; idx += 512) {
        int n = idx / 240, ti = idx - n * 240;
        long off = (long)(n0 + n) * 240 + ti;
        float a1 = 0.f, a2 = 0.f;
#pragma unroll
        for (int c = 0; c < 8; c++) {
            a1 += g_G1p[(long)c * 512 * 240 + off];
            a2 += g_G2p[(long)c * 512 * 240 + off];
        }
        S.Gs1[n][ti] = a1;
        S.Gs2[n][ti] = a2;
    }
    if (tid < 256) {
        int n = tid >> 4, t = tid & 15;
        S.r1s[n][t] = g_r1[(n0 + n) * 16 + t];
        S.c2s[n][t] = g_c2[(n0 + n) * 16 + t];
    }
    __syncthreads();

    int n = tid >> 5, d = tid & 31;
    float acc = 0.f;
#pragma unroll 16
    for (int ti = 0; ti < 240; ti++)
        acc += S.Gs1[n][ti] * S.W2sa[ti][d] + S.Gs2[n][ti] * S.W2sb[ti][d];

    int ng = n0 + n;
    const float* wa = g_XW2a + ng * 512 + d;
    const float* wb = g_XW2b + ng * 512 + d;
#pragma unroll
    for (int t = 0; t < 16; t++)
        acc += S.r1s[n][t] * wb[t * 32] + S.c2s[n][t] * wa[t * 32];
    acc += S.r1s[n][15] * wa[15 * 32] + S.c2s[n][15] * wb[15 * 32];

    out[ng * 32 + d] = fmaxf(acc, 0.2f * acc);
}

// ---------------- launch ----------------
extern "C" void kernel_launch(void* const* d_in, const int* in_sizes, int n_in,
                              void* d_out, int out_size) {
    const float* x   = (const float*)d_in[0];
    const float* adj = (const float*)d_in[1];
    const float* W1  = (const float*)d_in[2];
    const float* W2  = (const float*)d_in[3];
    const float* W3  = (const float*)d_in[4];
    float* out = (float*)d_out;
    (void)in_sizes; (void)n_in; (void)out_size;

    cudaFuncSetAttribute(k2_logits, cudaFuncAttributeMaxDynamicSharedMemorySize,
                         (int)sizeof(K2S));
    cudaFuncSetAttribute(kEpi, cudaFuncAttributeMaxDynamicSharedMemorySize,
                         (int)sizeof(EpiS));

    k1_precompute<<<128, 256>>>(x, W1, W2, W3);
    k2_logits<<<dim3(32, 32), 256, sizeof(K2S)>>>(adj, x);
    k5_softmax<<<1024, 256>>>();
    k6G<<<640, 480>>>(adj, x);
    kEpi<<<32, 512, sizeof(EpiS)>>>(out, W2);
}

// round 12
// speedup vs baseline: 1.0961x; 1.0961x over previous
#include <cuda_runtime.h>

#define NN 512
#define TP 16

typedef unsigned long long ull;

// ---------- f32x2 packed helpers ----------
__device__ __forceinline__ ull pk2(float lo, float hi) {
    ull r; asm("mov.b64 %0, {%1, %2};" : "=l"(r) : "f"(lo), "f"(hi)); return r;
}
__device__ __forceinline__ void upk2(float& lo, float& hi, ull v) {
    asm("mov.b64 {%0, %1}, %2;" : "=f"(lo), "=f"(hi) : "l"(v));
}
__device__ __forceinline__ void ffma2(ull& acc, ull a, ull b) {
    asm("fma.rn.f32x2 %0, %1, %2, %0;" : "+l"(acc) : "l"(a), "l"(b));
}

// ---------------- scratch ----------------
__device__ float g_XW1a[NN * TP * 32];
__device__ float g_XW1b[NN * TP * 32];
__device__ float g_XW2a[NN * TP * 32];
__device__ float g_XW2b[NN * TP * 32];
__device__ float g_Q[NN * 32];
__device__ float g_QB[NN * TP];
__device__ float g_RA[NN * TP];
__device__ float g_U1[NN * 256];    // U1[a][t*16+i] = sum_h Q[a,h] W1[i,t,h]
__device__ float g_U2[NN * 256];
__device__ float g_L1[NN * NN];     // logits1 -> s1
__device__ float g_L2T[NN * NN];    // logits2^T -> s2^T
__device__ float g_r1[NN * TP];
__device__ float g_c2[NN * TP];
__device__ float g_G1p[8 * NN * 240];
__device__ float g_G2p[8 * NN * 240];

// ---------------- k1: XW1a/b, XW2a/b, Q, QB, RA, U1/U2 ----------------
__global__ void k1_precompute(const float* __restrict__ x,
                              const float* __restrict__ W1,
                              const float* __restrict__ W2,
                              const float* __restrict__ W3) {
    int n0 = blockIdx.x * 4;
    __shared__ float xs[4][16];
    __shared__ float Qsm[4][32];
    int tid = threadIdx.x;
    if (tid < 64) xs[tid / 16][tid % 16] = x[(n0 + tid / 16) * 16 + (tid % 16)];
    __syncthreads();

    for (int th = tid; th < 512; th += 256) {
        float a1[4] = {0,0,0,0}, b1[4] = {0,0,0,0};
        float a2[4] = {0,0,0,0}, b2[4] = {0,0,0,0};
        for (int i = 0; i < 16; i++) {
            float w1a = W1[i * 512 + th];
            float w1b = W1[(i + 16) * 512 + th];
            float w2a = W2[i * 512 + th];
            float w2b = W2[(i + 16) * 512 + th];
#pragma unroll
            for (int j = 0; j < 4; j++) {
                float xv = xs[j][i];
                a1[j] += xv * w1a; b1[j] += xv * w1b;
                a2[j] += xv * w2a; b2[j] += xv * w2b;
            }
        }
#pragma unroll
        for (int j = 0; j < 4; j++) {
            g_XW1a[(n0 + j) * 512 + th] = a1[j];
            g_XW1b[(n0 + j) * 512 + th] = b1[j];
            g_XW2a[(n0 + j) * 512 + th] = a2[j];
            g_XW2b[(n0 + j) * 512 + th] = b2[j];
        }
    }
    if (tid < 32) {
#pragma unroll
        for (int j = 0; j < 4; j++) {
            float acc = 0.f;
            for (int i = 0; i < 16; i++) acc += xs[j][i] * W3[i * 32 + tid];
            g_Q[(n0 + j) * 32 + tid] = acc;
            Qsm[j][tid] = acc;
        }
    }
    __syncthreads();
    if (tid < 64) {
        int n = n0 + tid / 16, t = tid % 16;
        const float* q  = g_Q + n * 32;
        const float* wa = g_XW1a + n * 512 + t * 32;
        const float* wb = g_XW1b + n * 512 + t * 32;
        float ra = 0.f, qb = 0.f;
#pragma unroll
        for (int h = 0; h < 32; h++) { float qv = q[h]; ra += qv * wa[h]; qb += qv * wb[h]; }
        g_RA[n * 16 + t] = ra;
        g_QB[n * 16 + t] = qb;
    }
    // U1/U2
    {
        int t = tid >> 4, i = tid & 15;
        const float* w1a = W1 + i * 512 + t * 32;
        const float* w1b = W1 + (i + 16) * 512 + t * 32;
        float u1[4] = {0,0,0,0}, u2[4] = {0,0,0,0};
#pragma unroll 8
        for (int h = 0; h < 32; h++) {
            float wa_ = w1a[h], wb_ = w1b[h];
#pragma unroll
            for (int j = 0; j < 4; j++) {
                float qv = Qsm[j][h];
                u1[j] += qv * wa_;
                u2[j] += qv * wb_;
            }
        }
#pragma unroll
        for (int j = 0; j < 4; j++) {
            g_U1[(n0 + j) * 256 + t * 16 + i] = u1[j];
            g_U2[(n0 + j) * 256 + t * 16 + i] = u2[j];
        }
    }
}

// ---------------- k2: factored logits, thread-per-(a,b), no shuffles ----------------
struct K2S {
    ull U1p[16][17][8];
    ull U2p[16][17][8];
    float adjR[16][241];
    float adjC[16][241];
    ull xp[16][8];
    float QBs[16][16];
    float RAs[16][16];
};

__global__ void __launch_bounds__(256) k2_logits(const float* __restrict__ adj,
                                                 const float* __restrict__ x) {
    extern __shared__ char sraw[];
    K2S& S = *reinterpret_cast<K2S*>(sraw);
    int tid = threadIdx.x;
    int a0 = blockIdx.y * 16, b0 = blockIdx.x * 16;
    int bid = blockIdx.y * 32 + blockIdx.x;
    if (bid < 32)      g_r1[bid * 256 + tid] = 0.f;
    else if (bid < 64) g_c2[(bid - 32) * 256 + tid] = 0.f;

    for (int idx = tid; idx < 2048; idx += 256) {
        int a = idx >> 7, p = idx & 127;
        int t = p >> 3, ip = p & 7;
        float2 v1 = *(const float2*)(g_U1 + (a0 + a) * 256 + t * 16 + ip * 2);
        float2 v2 = *(const float2*)(g_U2 + (a0 + a) * 256 + t * 16 + ip * 2);
        S.U1p[a][t][ip] = pk2(v1.x, v1.y);
        S.U2p[a][t][ip] = pk2(v2.x, v2.y);
    }
    for (int idx = tid; idx < 960; idx += 256) {
        int r = idx / 60, q = (idx % 60) * 4;
        float4 vR = *(const float4*)(adj + ((long)(a0 + r) * 512 + b0) * 15 + q);
        float4 vC = *(const float4*)(adj + ((long)(b0 + r) * 512 + a0) * 15 + q);
        S.adjR[r][q] = vR.x; S.adjR[r][q+1] = vR.y; S.adjR[r][q+2] = vR.z; S.adjR[r][q+3] = vR.w;
        S.adjC[r][q] = vC.x; S.adjC[r][q+1] = vC.y; S.adjC[r][q+2] = vC.z; S.adjC[r][q+3] = vC.w;
    }
    if (tid < 128) {
        int b = tid >> 3, ip = tid & 7;
        float2 v = *(const float2*)(x + (b0 + b) * 16 + ip * 2);
        S.xp[b][ip] = pk2(v.x, v.y);
    }
    {
        int a = tid >> 4, t = tid & 15;
        S.QBs[a][t] = g_QB[(a0 + a) * 16 + t];
        S.RAs[a][t] = g_RA[(a0 + a) * 16 + t];
    }
    __syncthreads();

    int a = tid >> 4, bsub = tid & 15;
    int ag = a0 + a, bg = b0 + bsub;
    float diagF = (ag == bg) ? 1.f : 0.f;

    ull xr[8];
    {
        ulonglong2* d = (ulonglong2*)xr;
        const ulonglong2* s = (const ulonglong2*)S.xp[bsub];
        d[0] = s[0]; d[1] = s[1]; d[2] = s[2]; d[3] = s[3];
    }

    ull w1p[8];
#pragma unroll
    for (int ip = 0; ip < 8; ip++) w1p[ip] = 0ull;
    float accQB = 0.f;
#pragma unroll
    for (int t = 0; t < 16; t++) {
        float ar = (t < 15) ? S.adjR[a][bsub * 15 + t] : diagF;
        float ac = (t < 15) ? S.adjC[bsub][a * 15 + t] : diagF;
        ull arp = pk2(ar, ar);
        const ulonglong2* u = (const ulonglong2*)S.U1p[a][t];
        ulonglong2 u0 = u[0], u1 = u[1], u2 = u[2], u3 = u[3];
        ffma2(w1p[0], arp, u0.x); ffma2(w1p[1], arp, u0.y);
        ffma2(w1p[2], arp, u1.x); ffma2(w1p[3], arp, u1.y);
        ffma2(w1p[4], arp, u2.x); ffma2(w1p[5], arp, u2.y);
        ffma2(w1p[6], arp, u3.x); ffma2(w1p[7], arp, u3.y);
        accQB += ac * S.QBs[a][t];
    }
    {
        ull dot = 0ull;
#pragma unroll
        for (int ip = 0; ip < 8; ip++) ffma2(dot, xr[ip], w1p[ip]);
        float lo, hi; upk2(lo, hi, dot);
        g_L1[ag * 512 + bg] = lo + hi + accQB;
    }

    ull w2p[8];
#pragma unroll
    for (int ip = 0; ip < 8; ip++) w2p[ip] = 0ull;
    float accRA = 0.f;
#pragma unroll
    for (int t = 0; t < 16; t++) {
        float ar = (t < 15) ? S.adjR[a][bsub * 15 + t] : diagF;
        float ac = (t < 15) ? S.adjC[bsub][a * 15 + t] : diagF;
        ull arp = pk2(ar, ar);
        const ulonglong2* u = (const ulonglong2*)S.U2p[a][t];
        ulonglong2 u0 = u[0], u1 = u[1], u2 = u[2], u3 = u[3];
        ffma2(w2p[0], arp, u0.x); ffma2(w2p[1], arp, u0.y);
        ffma2(w2p[2], arp, u1.x); ffma2(w2p[3], arp, u1.y);
        ffma2(w2p[4], arp, u2.x); ffma2(w2p[5], arp, u2.y);
        ffma2(w2p[6], arp, u3.x); ffma2(w2p[7], arp, u3.y);
        accRA += ac * S.RAs[a][t];
    }
    {
        ull dot = 0ull;
#pragma unroll
        for (int ip = 0; ip < 8; ip++) ffma2(dot, xr[ip], w2p[ip]);
        float lo, hi; upk2(lo, hi, dot);
        g_L2T[ag * 512 + bg] = lo + hi + accRA;
    }
}

// ---------------- k5: row softmax ----------------
__global__ void k5_softmax() {
    int r = blockIdx.x;
    float* row = (r < 512) ? (g_L1 + r * 512) : (g_L2T + (r - 512) * 512);
    int tid = threadIdx.x;
    __shared__ float red[8];
    float v0 = row[tid], v1 = row[tid + 256];
    float m = fmaxf(v0, v1);
#pragma unroll
    for (int o = 16; o; o >>= 1) m = fmaxf(m, __shfl_xor_sync(0xffffffffu, m, o));
    if ((tid & 31) == 0) red[tid >> 5] = m;
    __syncthreads();
    float bm = red[0];
#pragma unroll
    for (int i = 1; i < 8; i++) bm = fmaxf(bm, red[i]);
    float e0 = __expf(v0 - bm), e1 = __expf(v1 - bm);
    float s = e0 + e1;
#pragma unroll
    for (int o = 16; o; o >>= 1) s += __shfl_xor_sync(0xffffffffu, s, o);
    __syncthreads();
    if ((tid & 31) == 0) red[tid >> 5] = s;
    __syncthreads();
    float bs = red[0] + red[1] + red[2] + red[3] + red[4] + red[5] + red[6] + red[7];
    float inv = 1.0f / bs;
    row[tid] = e0 * inv;
    row[tid + 256] = e1 * inv;
}

// ---------------- k6r: r1/c2 via transpose-tiled coalesced adj reads ----------------
__global__ void __launch_bounds__(480) k6r_rc(const float* __restrict__ adj) {
    int m0 = blockIdx.x * 16;
    int n0 = blockIdx.y * 32;
    int tid = threadIdx.x;
    __shared__ float s1s[32][17], s2s[32][17];
    for (int idx = tid; idx < 512; idx += 480) {
        int n = idx >> 4, ml = idx & 15;
        s1s[n][ml] = g_L1[(n0 + n) * 512 + m0 + ml];
        s2s[n][ml] = g_L2T[(n0 + n) * 512 + m0 + ml];
    }
    __syncthreads();

    int dn = m0 - n0;
    if ((dn == 0 || dn == 16) && tid < 16) {
        int n = dn + tid;
        atomicAdd(&g_r1[(n0 + n) * 16 + 15], s1s[n][tid]);
        atomicAdd(&g_c2[(n0 + n) * 16 + 15], s2s[n][tid]);
    }

    int n = tid / 15, t = tid - n * 15;
    const float* base = adj + ((long)m0 * 512 + n0) * 15 + tid;
    float r1p = 0.f, c2p = 0.f;
#pragma unroll
    for (int ml = 0; ml < 16; ml++) {
        float v = __ldg(base + ml * 7680);
        r1p += s1s[n][ml] * v;
        c2p += s2s[n][ml] * v;
    }
    atomicAdd(&g_r1[(n0 + n) * 16 + t], r1p);
    atomicAdd(&g_c2[(n0 + n) * 16 + t], c2p);
}

// ---------------- kG: G[n,t,i] = sum_m (s*adj)[n,m,t] x[m,i] ----------------
__global__ void __launch_bounds__(480) kG(const float* __restrict__ adj,
                                          const float* __restrict__ x) {
    int m0 = blockIdx.x * 64;
    int n0 = blockIdx.y * 32;
    int tid = threadIdx.x;
    __shared__ float s1s[32][64], s2s[32][64];
    __shared__ ull xp[64][8];

    for (int idx = tid; idx < 2048; idx += 480) {
        int n = idx >> 6, ml = idx & 63;
        s1s[n][ml] = g_L1[(n0 + n) * 512 + m0 + ml];
        s2s[n][ml] = g_L2T[(n0 + n) * 512 + m0 + ml];
    }
    for (int idx = tid; idx < 512; idx += 480) {
        int ml = idx >> 3, ip = idx & 7;
        float2 v = *(const float2*)(x + (m0 + ml) * 16 + ip * 2);
        xp[ml][ip] = pk2(v.x, v.y);
    }
    __syncthreads();

    int n = tid / 15, t = tid - n * 15;
    ull G1[8], G2[8];
#pragma unroll
    for (int ip = 0; ip < 8; ip++) { G1[ip] = 0ull; G2[ip] = 0ull; }

    const float* ap = adj + (long)(n0 + n) * 7680 + (long)m0 * 15 + t;
#pragma unroll 8
    for (int ml = 0; ml < 64; ml++) {
        float av = __ldg(ap + ml * 15);
        float p1 = s1s[n][ml] * av;
        float p2 = s2s[n][ml] * av;
        ull p1p = pk2(p1, p1), p2p = pk2(p2, p2);
#pragma unroll
        for (int ip = 0; ip < 8; ip++) {
            ull xv = xp[ml][ip];
            ffma2(G1[ip], p1p, xv);
            ffma2(G2[ip], p2p, xv);
        }
    }
    long base = ((long)blockIdx.x * 512 + n0 + n) * 240 + t * 16;
    float* d1 = g_G1p + base;
    float* d2 = g_G2p + base;
#pragma unroll
    for (int q = 0; q < 4; q++) {
        ulonglong2 v1; v1.x = G1[2 * q]; v1.y = G1[2 * q + 1];
        ulonglong2 v2; v2.x = G2[2 * q]; v2.y = G2[2 * q + 1];
        *(ulonglong2*)(d1 + q * 4) = v1;
        *(ulonglong2*)(d2 + q * 4) = v2;
    }
}

// ---------------- kEpi: reduce G partials + tiny GEMM + r1/c2 tail + lrelu ----------------
struct EpiS {
    float Gs1[16][240];
    float Gs2[16][240];
    float W2sa[240][32];
    float W2sb[240][32];
    float r1s[16][16], c2s[16][16];
};

__global__ void __launch_bounds__(512) kEpi(float* __restrict__ out,
                                            const float* __restrict__ W2) {
    extern __shared__ char smem_raw[];
    EpiS& S = *reinterpret_cast<EpiS*>(smem_raw);
    int n0 = blockIdx.x * 16;
    int tid = threadIdx.x;

    for (int idx = tid; idx < 7680; idx += 512) {
        int ti = idx >> 5, d = idx & 31;
        int i = ti & 15, t = ti >> 4;
        S.W2sa[ti][d] = W2[i * 512 + t * 32 + d];
        S.W2sb[ti][d] = W2[(i + 16) * 512 + t * 32 + d];
    }
    for (int idx = tid; idx < 3840; idx += 512) {
        int n = idx / 240, ti = idx - n * 240;
        long off = (long)(n0 + n) * 240 + ti;
        float a1 = 0.f, a2 = 0.f;
#pragma unroll
        for (int c = 0; c < 8; c++) {
            a1 += g_G1p[(long)c * 512 * 240 + off];
            a2 += g_G2p[(long)c * 512 * 240 + off];
        }
        S.Gs1[n][ti] = a1;
        S.Gs2[n][ti] = a2;
    }
    if (tid < 256) {
        int n = tid >> 4, t = tid & 15;
        S.r1s[n][t] = g_r1[(n0 + n) * 16 + t];
        S.c2s[n][t] = g_c2[(n0 + n) * 16 + t];
    }
    __syncthreads();

    int n = tid >> 5, d = tid & 31;
    float acc = 0.f;
#pragma unroll 16
    for (int ti = 0; ti < 240; ti++)
        acc += S.Gs1[n][ti] * S.W2sa[ti][d] + S.Gs2[n][ti] * S.W2sb[ti][d];

    int ng = n0 + n;
    const float* wa = g_XW2a + ng * 512 + d;
    const float* wb = g_XW2b + ng * 512 + d;
#pragma unroll
    for (int t = 0; t < 16; t++)
        acc += S.r1s[n][t] * wb[t * 32] + S.c2s[n][t] * wa[t * 32];
    acc += S.r1s[n][15] * wa[15 * 32] + S.c2s[n][15] * wb[15 * 32];

    out[ng * 32 + d] = fmaxf(acc, 0.2f * acc);
}

// ---------------- launch ----------------
extern "C" void kernel_launch(void* const* d_in, const int* in_sizes, int n_in,
                              void* d_out, int out_size) {
    const float* x   = (const float*)d_in[0];
    const float* adj = (const float*)d_in[1];
    const float* W1  = (const float*)d_in[2];
    const float* W2  = (const float*)d_in[3];
    const float* W3  = (const float*)d_in[4];
    float* out = (float*)d_out;
    (void)in_sizes; (void)n_in; (void)out_size;

    cudaFuncSetAttribute(k2_logits, cudaFuncAttributeMaxDynamicSharedMemorySize,
                         (int)sizeof(K2S));
    cudaFuncSetAttribute(kEpi, cudaFuncAttributeMaxDynamicSharedMemorySize,
                         (int)sizeof(EpiS));

    k1_precompute<<<128, 256>>>(x, W1, W2, W3);
    k2_logits<<<dim3(32, 32), 256, sizeof(K2S)>>>(adj, x);
    k5_softmax<<<1024, 256>>>();
    k6r_rc<<<dim3(32, 16), 480>>>(adj);
    kG<<<dim3(8, 16), 480>>>(adj, x);
    kEpi<<<32, 512, sizeof(EpiS)>>>(out, W2);
}